// round 11
// baseline (speedup 1.0000x reference)
#include <cuda_runtime.h>
#include <cuda_bf16.h>
#include <cstdint>

// out[b,f] = -2.5*log10( sum_l A[b,l] * (trans[f,l]*w[l]) )
// wt_kernel -> g_wt bf16 [F,L] (2MB, L2-resident)
// gemm_log_kernel: BM=64 BN=128 BK=64, 256 thr, grid 128.
//   8 warps = 2 warp-tiles (64x64, N-halves) x 4-way K16 split (kh=warp&3).
//   Per warp per k-tile: 8 ldmatrix -> 32 independent mma (0.25 ldm/mma).
//   A: LDG->bf16->STS (conflict-free 128B rows); B: 6-slot cp.async ring;
//   one barrier per PAIR of k-tiles. Final 4-way merge via smem + log10.
// Ruled out: split-K via gmem (2x), 16-row warp tiles (frag x1.5), BK=128 /
//   256B rows (bank conflicts), manual frag double-buffer (regs).
//   tcgen05 rejected by ptxas (compute_103 target).

#define BM 64
#define BN 128
#define BK 64
#define THREADS 256
#define B_ST   16384                 // BN*BK*2
#define ABF_ST 8192                  // BM*BK*2
#define NB_ST  6
#define OFF_ABF (NB_ST * B_ST)                     // 96KB
#define DYN_SMEM (OFF_ABF + 4 * ABF_ST + 1024)     // 129KB

__device__ __align__(16) __nv_bfloat16 g_wt[128 * 8192];

__global__ void wt_kernel(const float* __restrict__ trans,
                          const float* __restrict__ lam, int F, int L) {
    int i4 = blockIdx.x * blockDim.x + threadIdx.x;
    int total = (F * L) >> 2;
    if (i4 >= total) return;
    int l0 = (i4 % (L >> 2)) << 2;
    float4 t = reinterpret_cast<const float4*>(trans)[i4];
    float w[4];
#pragma unroll
    for (int j = 0; j < 4; j++) {
        int l = l0 + j;
        int hi = l + 1 < L ? l + 1 : L - 1;
        int lo = l > 0 ? l - 1 : 0;
        w[j] = 0.5f * (__ldg(lam + hi) - __ldg(lam + lo));
    }
    __nv_bfloat162 p0 = __floats2bfloat162_rn(t.x * w[0], t.y * w[1]);
    __nv_bfloat162 p1 = __floats2bfloat162_rn(t.z * w[2], t.w * w[3]);
    uint2 v = { reinterpret_cast<uint32_t&>(p0), reinterpret_cast<uint32_t&>(p1) };
    reinterpret_cast<uint2*>(g_wt)[i4] = v;
}

__device__ __forceinline__ uint32_t smem_u32(const void* p) {
    uint32_t a;
    asm("{ .reg .u64 t; cvta.to.shared.u64 t, %1; cvt.u32.u64 %0, t; }"
        : "=r"(a) : "l"(p));
    return a;
}
__device__ __forceinline__ void ldmx4(uint32_t* r, uint32_t addr) {
    asm volatile("ldmatrix.sync.aligned.m8n8.x4.shared.b16 {%0,%1,%2,%3}, [%4];\n"
                 : "=r"(r[0]), "=r"(r[1]), "=r"(r[2]), "=r"(r[3]) : "r"(addr));
}
__device__ __forceinline__ void mma16816(float* c, const uint32_t* a, const uint32_t* b) {
    asm volatile("mma.sync.aligned.m16n8k16.row.col.f32.bf16.bf16.f32 "
                 "{%0,%1,%2,%3}, {%4,%5,%6,%7}, {%8,%9}, {%0,%1,%2,%3};\n"
                 : "+f"(c[0]), "+f"(c[1]), "+f"(c[2]), "+f"(c[3])
                 : "r"(a[0]), "r"(a[1]), "r"(a[2]), "r"(a[3]), "r"(b[0]), "r"(b[1]));
}
__device__ __forceinline__ uint32_t packbf2(float x, float y) {
    __nv_bfloat162 h = __floats2bfloat162_rn(x, y);
    return reinterpret_cast<uint32_t&>(h);
}
__device__ __forceinline__ void cp16(uint32_t dst, const void* src) {
    asm volatile("cp.async.cg.shared.global [%0], [%1], 16;"
                 :: "r"(dst), "l"(src) : "memory");
}
#define CP_COMMIT() asm volatile("cp.async.commit_group;" ::: "memory")
#define CP_WAIT1()  asm volatile("cp.async.wait_group 1;" ::: "memory")

__global__ void __launch_bounds__(THREADS, 1)
gemm_log_kernel(const float* __restrict__ A, float* __restrict__ out, int K) {
    extern __shared__ char dynsmem[];
    const uint32_t base = (smem_u32(dynsmem) + 1023) & ~1023u;
    const uint32_t bB   = base;
    const uint32_t bAbf = base + OFF_ABF;

    const int tid  = threadIdx.x;
    const int lane = tid & 31;
    const int warp = tid >> 5;        // 0..7
    const int wt   = warp >> 2;       // N-half 0/1
    const int kh   = warp & 3;        // K16 step owned within each BK tile
    const size_t bm0 = (size_t)blockIdx.x * BM;
    const int NKT = K / BK;           // 128
    const int NP  = NKT >> 1;         // 64 pairs

    // ---- A LDG/STS mapping (R9): row ar=tid>>2, 4 float4 at cols 16*(tid&3)
    const int ar = tid >> 2, ac = tid & 3;
    const float4* aSrc4 = reinterpret_cast<const float4*>(A + (bm0 + ar) * (size_t)K)
                        + 4 * ac;
    const uint32_t abfrel0 = (uint32_t)ar * 128 + (uint32_t)(((2 * ac)     ^ (ar & 7)) * 16);
    const uint32_t abfrel1 = (uint32_t)ar * 128 + (uint32_t)(((2 * ac + 1) ^ (ar & 7)) * 16);

    // ---- B cp mapping (R9): 4 chunks/thread/tile, conflict-free 128B rows
    uint32_t brel[4];
    const __nv_bfloat16* bsrc[4];
#pragma unroll
    for (int j = 0; j < 4; j++) {
        int id = tid + 256 * j;
        int n = id >> 3, cc = id & 7;
        brel[j] = (uint32_t)(n * 128 + ((cc ^ (n & 7)) * 16));
        bsrc[j] = g_wt + (size_t)n * K + cc * 8;
    }

    // ---- fragment rows: A all 64 rows (4 frag groups), B 64 cols of N-half
    int arow[4], brow[4];
#pragma unroll
    for (int f = 0; f < 4; f++) {
        arow[f] = f * 16 + (lane & 15);
        brow[f] = wt * 64 + f * 16 + ((lane >> 4) << 3) + (lane & 7);
    }
    const int achalf = lane >> 4;
    const int bchalf = (lane >> 3) & 1;
    const int ca = kh * 2 + achalf;    // A smem chunk col for this warp
    const int cb = kh * 2 + bchalf;    // B smem chunk col

    float acc[4][8][4];                // 64x64 warp tile partial (one K16 lane)
#pragma unroll
    for (int i = 0; i < 4; i++)
#pragma unroll
        for (int j = 0; j < 8; j++)
#pragma unroll
            for (int k = 0; k < 4; k++) acc[i][j][k] = 0.f;

    float4 fa[4];                      // single-tile A prefetch

#define LOAD_A_TILE(T) do {                                                   \
        const float4* _p = aSrc4 + (size_t)(T) * (BK >> 2);                   \
        fa[0] = __ldg(_p);     fa[1] = __ldg(_p + 1);                         \
        fa[2] = __ldg(_p + 2); fa[3] = __ldg(_p + 3);                         \
    } while (0)

#define CONVERT_TILE(T) do {                                                  \
        const uint32_t _da = bAbf + (uint32_t)((T) & 3) * ABF_ST;             \
        asm volatile("st.shared.v4.b32 [%0], {%1,%2,%3,%4};" ::               \
            "r"(_da + abfrel0),                                               \
            "r"(packbf2(fa[0].x, fa[0].y)), "r"(packbf2(fa[0].z, fa[0].w)),   \
            "r"(packbf2(fa[1].x, fa[1].y)), "r"(packbf2(fa[1].z, fa[1].w)) : "memory"); \
        asm volatile("st.shared.v4.b32 [%0], {%1,%2,%3,%4};" ::               \
            "r"(_da + abfrel1),                                               \
            "r"(packbf2(fa[2].x, fa[2].y)), "r"(packbf2(fa[2].z, fa[2].w)),   \
            "r"(packbf2(fa[3].x, fa[3].y)), "r"(packbf2(fa[3].z, fa[3].w)) : "memory"); \
    } while (0)

#define ISSUE_B_PAIR(P, S0) do {                                              \
        const uint32_t _b0 = bB + (uint32_t)(S0) * B_ST;                      \
        const uint32_t _b1 = _b0 + B_ST;                                      \
        const size_t _o0 = (size_t)(2 * (P)) * BK;                            \
        _Pragma("unroll")                                                     \
        for (int _j = 0; _j < 4; _j++) {                                      \
            cp16(_b0 + brel[_j], bsrc[_j] + _o0);                             \
            cp16(_b1 + brel[_j], bsrc[_j] + _o0 + BK);                        \
        }                                                                     \
    } while (0)

    // this warp's one K16 step of a k-tile: 8 ldmatrix -> 32 mma
#define COMPUTE_TILE(AOFF, BOFF) do {                                         \
        uint32_t a[4][4], b[4][4];                                            \
        _Pragma("unroll")                                                     \
        for (int _f = 0; _f < 4; _f++)                                        \
            ldmx4(a[_f], (AOFF) + (uint32_t)(arow[_f] * 8 + (ca ^ (arow[_f] & 7))) * 16); \
        _Pragma("unroll")                                                     \
        for (int _f = 0; _f < 4; _f++)                                        \
            ldmx4(b[_f], (BOFF) + (uint32_t)(brow[_f] * 8 + (cb ^ (brow[_f] & 7))) * 16); \
        _Pragma("unroll")                                                     \
        for (int _mi = 0; _mi < 4; _mi++)                                     \
            _Pragma("unroll")                                                 \
            for (int _nt = 0; _nt < 8; _nt++)                                 \
                mma16816(acc[_mi][_nt], a[_mi], &b[_nt >> 1][(_nt & 1) * 2]); \
    } while (0)

    // ---------- prologue ----------
    LOAD_A_TILE(0);
    ISSUE_B_PAIR(0, 0); CP_COMMIT();
    ISSUE_B_PAIR(1, 2); CP_COMMIT();
    CONVERT_TILE(0);
    LOAD_A_TILE(1);
    CONVERT_TILE(1);
    CP_WAIT1();
    __syncthreads();

    int sB = 0, sBiss = 4;

    // ---------- main loop: one barrier per PAIR ----------
    for (int p = 0; p < NP; p++) {
        if (p + 2 < NP) ISSUE_B_PAIR(p + 2, sBiss);
        CP_COMMIT();
        if (p + 1 < NP) LOAD_A_TILE(2 * p + 2);

        const uint32_t a0 = bAbf + (uint32_t)((2 * p) & 3) * ABF_ST;
        const uint32_t a1 = bAbf + (uint32_t)((2 * p + 1) & 3) * ABF_ST;
        const uint32_t b0 = bB + (uint32_t)sB * B_ST;
        const uint32_t b1 = b0 + B_ST;

        COMPUTE_TILE(a0, b0);
        if (p + 1 < NP) { CONVERT_TILE(2 * p + 2); LOAD_A_TILE(2 * p + 3); }
        COMPUTE_TILE(a1, b1);
        if (p + 1 < NP) CONVERT_TILE(2 * p + 3);

        CP_WAIT1();
        __syncthreads();

        sB    = (sB    == 4) ? 0 : sB + 2;
        sBiss = (sBiss == 4) ? 0 : sBiss + 2;
    }

    // ---------- 4-way k-split merge + epilogue ----------
    // region(wt, j) = base + (wt*4 + j)*16KB ; block (mi,nt) at +((mi*8+nt)*512 + lane*16)
    const uint32_t regOwn = base + (uint32_t)(wt * 4 + kh) * 16384 + (uint32_t)lane * 16;
#pragma unroll
    for (int mi = 0; mi < 4; mi++)
#pragma unroll
        for (int nt = 0; nt < 8; nt++)
            asm volatile("st.shared.v4.b32 [%0], {%1,%2,%3,%4};" ::
                "r"(regOwn + (uint32_t)((mi * 8 + nt) * 512)),
                "r"(__float_as_uint(acc[mi][nt][0])), "r"(__float_as_uint(acc[mi][nt][1])),
                "r"(__float_as_uint(acc[mi][nt][2])), "r"(__float_as_uint(acc[mi][nt][3]))
                : "memory");
    __syncthreads();

    // warp (wt, kh) finalizes output rows [kh*16, kh*16+16), cols [wt*64, wt*64+64)
    const float C = -0.75257498915995302f;   // -2.5 / log2(10)
    const size_t row0 = bm0 + kh * 16 + (lane >> 2);
#pragma unroll
    for (int nt = 0; nt < 8; nt++) {
        float s0 = acc[kh][nt][0], s1 = acc[kh][nt][1];
        float s2 = acc[kh][nt][2], s3 = acc[kh][nt][3];
#pragma unroll
        for (int j = 0; j < 4; j++) {
            if (j == kh) continue;
            float p0, p1, p2, p3;
            asm volatile("ld.shared.v4.f32 {%0,%1,%2,%3}, [%4];"
                : "=f"(p0), "=f"(p1), "=f"(p2), "=f"(p3)
                : "r"(base + (uint32_t)(wt * 4 + j) * 16384 +
                      (uint32_t)((kh * 8 + nt) * 512) + (uint32_t)lane * 16));
            s0 += p0; s1 += p1; s2 += p2; s3 += p3;
        }
        const int col = wt * 64 + nt * 8 + (lane & 3) * 2;
        float2 v0, v1;
        v0.x = C * __log2f(s0);
        v0.y = C * __log2f(s1);
        v1.x = C * __log2f(s2);
        v1.y = C * __log2f(s3);
        *reinterpret_cast<float2*>(out + row0 * BN + col)       = v0;
        *reinterpret_cast<float2*>(out + (row0 + 8) * BN + col) = v1;
    }
}

extern "C" void kernel_launch(void* const* d_in, const int* in_sizes, int n_in,
                              void* d_out, int out_size) {
    const float* l_target = (const float*)d_in[0];   // [B, L] fp32
    const float* trans    = (const float*)d_in[1];   // [F, L] fp32
    const float* lam      = (const float*)d_in[2];   // [L]    fp32

    const int L = in_sizes[2];
    const int F = in_sizes[1] / L;   // 128
    const int B = in_sizes[0] / L;   // 8192
    float* out = (float*)d_out;

    cudaFuncSetAttribute(gemm_log_kernel,
                         cudaFuncAttributeMaxDynamicSharedMemorySize, DYN_SMEM);

    int total4 = (F * L) >> 2;
    wt_kernel<<<(total4 + 255) / 256, 256>>>(trans, lam, F, L);
    gemm_log_kernel<<<B / BM, THREADS, DYN_SMEM>>>(l_target, out, L);
}

// round 12
// speedup vs baseline: 2.5839x; 2.5839x over previous
#include <cuda_runtime.h>
#include <cuda_bf16.h>
#include <cstdint>

// out[b,f] = -2.5*log10( sum_l A[b,l] * (trans[f,l]*w[l]) )
// wt_kernel -> g_wt bf16 [F,L] (2MB, L2-resident)
// gemm_log_kernel: R10 core (BM=64 BN=128 BK=64, 32x32 warp tiles x warp-pair
//   k-split, conflict-free 128B rows, 6-slot B ring, 1 barrier/pair) +
//   WARP SPECIALIZATION: warps 0-15 compute only; warps 16-19 stage A
//   (LDG->bf16->STS) and issue B cp.async. 640 threads, 5 warps/SMSP.
// Ruled out: gmem split-K (2x), 16-row tiles (frag x1.5), BK=128/256B rows
//   (bank conflicts), 64x64 tiles @256thr (regs=255 spill, R11), manual frag
//   double-buffer. tcgen05 rejected by ptxas (compute_103 target).

#define BM 64
#define BN 128
#define BK 64
#define THREADS 640
#define NCOMPUTE 512                  // warps 0..15 compute
#define B_ST   16384                  // BN*BK*2
#define ABF_ST 8192                   // BM*BK*2
#define NB_ST  6
#define OFF_ABF (NB_ST * B_ST)                     // 96KB
#define DYN_SMEM (OFF_ABF + 4 * ABF_ST + 1024)     // 129KB

__device__ __align__(16) __nv_bfloat16 g_wt[128 * 8192];

__global__ void wt_kernel(const float* __restrict__ trans,
                          const float* __restrict__ lam, int F, int L) {
    int i4 = blockIdx.x * blockDim.x + threadIdx.x;
    int total = (F * L) >> 2;
    if (i4 >= total) return;
    int l0 = (i4 % (L >> 2)) << 2;
    float4 t = reinterpret_cast<const float4*>(trans)[i4];
    float w[4];
#pragma unroll
    for (int j = 0; j < 4; j++) {
        int l = l0 + j;
        int hi = l + 1 < L ? l + 1 : L - 1;
        int lo = l > 0 ? l - 1 : 0;
        w[j] = 0.5f * (__ldg(lam + hi) - __ldg(lam + lo));
    }
    __nv_bfloat162 p0 = __floats2bfloat162_rn(t.x * w[0], t.y * w[1]);
    __nv_bfloat162 p1 = __floats2bfloat162_rn(t.z * w[2], t.w * w[3]);
    uint2 v = { reinterpret_cast<uint32_t&>(p0), reinterpret_cast<uint32_t&>(p1) };
    reinterpret_cast<uint2*>(g_wt)[i4] = v;
}

__device__ __forceinline__ uint32_t smem_u32(const void* p) {
    uint32_t a;
    asm("{ .reg .u64 t; cvta.to.shared.u64 t, %1; cvt.u32.u64 %0, t; }"
        : "=r"(a) : "l"(p));
    return a;
}
__device__ __forceinline__ void ldmx4(uint32_t* r, uint32_t addr) {
    asm volatile("ldmatrix.sync.aligned.m8n8.x4.shared.b16 {%0,%1,%2,%3}, [%4];\n"
                 : "=r"(r[0]), "=r"(r[1]), "=r"(r[2]), "=r"(r[3]) : "r"(addr));
}
__device__ __forceinline__ void mma16816(float* c, const uint32_t* a, const uint32_t* b) {
    asm volatile("mma.sync.aligned.m16n8k16.row.col.f32.bf16.bf16.f32 "
                 "{%0,%1,%2,%3}, {%4,%5,%6,%7}, {%8,%9}, {%0,%1,%2,%3};\n"
                 : "+f"(c[0]), "+f"(c[1]), "+f"(c[2]), "+f"(c[3])
                 : "r"(a[0]), "r"(a[1]), "r"(a[2]), "r"(a[3]), "r"(b[0]), "r"(b[1]));
}
__device__ __forceinline__ uint32_t packbf2(float x, float y) {
    __nv_bfloat162 h = __floats2bfloat162_rn(x, y);
    return reinterpret_cast<uint32_t&>(h);
}
__device__ __forceinline__ void cp16(uint32_t dst, const void* src) {
    asm volatile("cp.async.cg.shared.global [%0], [%1], 16;"
                 :: "r"(dst), "l"(src) : "memory");
}
#define CP_COMMIT() asm volatile("cp.async.commit_group;" ::: "memory")
#define CP_WAIT1()  asm volatile("cp.async.wait_group 1;" ::: "memory")

__global__ void __launch_bounds__(THREADS, 1)
gemm_log_kernel(const float* __restrict__ A, float* __restrict__ out, int K) {
    extern __shared__ char dynsmem[];
    const uint32_t base = (smem_u32(dynsmem) + 1023) & ~1023u;
    const uint32_t bB   = base;
    const uint32_t bAbf = base + OFF_ABF;

    const int tid  = threadIdx.x;
    const int lane = tid & 31;
    const int warp = tid >> 5;        // 0..19
    const bool isCompute = (warp < 16);
    const size_t bm0 = (size_t)blockIdx.x * BM;
    const int NKT = K / BK;           // 128
    const int NP  = NKT >> 1;         // 64 pairs

    // ================= compute-warp state =================
    const int wt = warp >> 1;         // warp-tile 0..7 (valid for compute)
    const int kh = warp & 1;          // k-half
    const int wmBase = (wt & 1) * 32;
    const int wnBase = (wt >> 1) * 32;
    int arow[2], brow[2];
#pragma unroll
    for (int mi = 0; mi < 2; mi++) arow[mi] = wmBase + mi * 16 + (lane & 15);
#pragma unroll
    for (int nj = 0; nj < 2; nj++) brow[nj] = wnBase + nj * 16 + ((lane >> 4) << 3) + (lane & 7);
    const int achalf = lane >> 4;
    const int bchalf = (lane >> 3) & 1;
    const int ks0 = kh * 2;

    float acc[2][4][4];
#pragma unroll
    for (int i = 0; i < 2; i++)
#pragma unroll
        for (int j = 0; j < 4; j++)
#pragma unroll
            for (int k = 0; k < 4; k++) acc[i][j][k] = 0.f;

    // ================= producer-warp state =================
    // 128 producer threads (warps 16-19): q = tid - 512
    const int q = tid - NCOMPUTE;                 // 0..127 (valid for producers)
    const int par = (q >> 1) & 63;                // A row 0..63
    const int pah = q & 1;                        // col half: 32 fp32
    const float4* aSrc4 = reinterpret_cast<const float4*>(A + (bm0 + par) * (size_t)K)
                        + 8 * pah;
    uint32_t abfrel[4];                           // 4 bf16 chunks owned
#pragma unroll
    for (int j = 0; j < 4; j++)
        abfrel[j] = (uint32_t)par * 128 + (uint32_t)(((4 * pah + j) ^ (par & 7)) * 16);

    uint32_t brel[8];
    const __nv_bfloat16* bsrc[8];
#pragma unroll
    for (int j = 0; j < 8; j++) {
        int id = q + 128 * j;                     // 0..1023
        int n = id >> 3, cc = id & 7;
        brel[j] = (uint32_t)(n * 128 + ((cc ^ (n & 7)) * 16));
        bsrc[j] = g_wt + (size_t)n * K + cc * 8;
    }

    // producer: LDG one A tile (8 float4), convert, STS into slot (T&3)
#define STAGE_A_TILE(T) do {                                                  \
        const float4* _p = aSrc4 + (size_t)(T) * (BK >> 2);                   \
        float4 _f[8];                                                         \
        _Pragma("unroll")                                                     \
        for (int _j = 0; _j < 8; _j++) _f[_j] = __ldg(_p + _j);               \
        const uint32_t _da = bAbf + (uint32_t)((T) & 3) * ABF_ST;             \
        _Pragma("unroll")                                                     \
        for (int _j = 0; _j < 4; _j++) {                                      \
            float4 _x = _f[2 * _j], _y = _f[2 * _j + 1];                      \
            asm volatile("st.shared.v4.b32 [%0], {%1,%2,%3,%4};" ::           \
                "r"(_da + abfrel[_j]),                                        \
                "r"(packbf2(_x.x, _x.y)), "r"(packbf2(_x.z, _x.w)),           \
                "r"(packbf2(_y.x, _y.y)), "r"(packbf2(_y.z, _y.w)) : "memory"); \
        }                                                                     \
    } while (0)

#define ISSUE_B_PAIR(P, S0) do {                                              \
        const uint32_t _b0 = bB + (uint32_t)(S0) * B_ST;                      \
        const uint32_t _b1 = _b0 + B_ST;                                      \
        const size_t _o0 = (size_t)(2 * (P)) * BK;                            \
        _Pragma("unroll")                                                     \
        for (int _j = 0; _j < 8; _j++) {                                      \
            cp16(_b0 + brel[_j], bsrc[_j] + _o0);                             \
            cp16(_b1 + brel[_j], bsrc[_j] + _o0 + BK);                        \
        }                                                                     \
    } while (0)

    // compute: this warp's 2 K16 steps of one k-tile
#define COMPUTE_TILE(AOFF, BOFF) do {                                         \
        _Pragma("unroll")                                                     \
        for (int _s = 0; _s < 2; _s++) {                                      \
            const int ks = ks0 + _s;                                          \
            uint32_t a[2][4], b[2][4];                                        \
            _Pragma("unroll")                                                 \
            for (int mi = 0; mi < 2; mi++) {                                  \
                int c = ks * 2 + achalf;                                      \
                ldmx4(a[mi], (AOFF) + (uint32_t)(arow[mi] * 8 + (c ^ (arow[mi] & 7))) * 16); \
            }                                                                 \
            _Pragma("unroll")                                                 \
            for (int nj = 0; nj < 2; nj++) {                                  \
                int c = ks * 2 + bchalf;                                      \
                ldmx4(b[nj], (BOFF) + (uint32_t)(brow[nj] * 8 + (c ^ (brow[nj] & 7))) * 16); \
            }                                                                 \
            _Pragma("unroll")                                                 \
            for (int mi = 0; mi < 2; mi++)                                    \
                _Pragma("unroll")                                             \
                for (int nt = 0; nt < 4; nt++)                                \
                    mma16816(acc[mi][nt], a[mi], &b[nt >> 1][(nt & 1) * 2]);  \
        }                                                                     \
    } while (0)

    // ---------- prologue ----------
    if (!isCompute) {
        ISSUE_B_PAIR(0, 0); CP_COMMIT();
        ISSUE_B_PAIR(1, 2); CP_COMMIT();
        STAGE_A_TILE(0);
        STAGE_A_TILE(1);
        STAGE_A_TILE(2);
        STAGE_A_TILE(3);
        CP_WAIT1();            // B pair 0 complete
    }
    __syncthreads();

    int sB = 0, sBiss = 4;

    // ---------- main loop: one barrier per PAIR of k-tiles ----------
    for (int p = 0; p < NP; p++) {
        if (!isCompute) {
            if (p + 2 < NP) ISSUE_B_PAIR(p + 2, sBiss);
            CP_COMMIT();
            if (p + 2 < NP) {        // A tiles 2p+4, 2p+5 -> slots free after this barrier? no:
                // slots (2p+4)&3 == (2p)&3 : compute reads (2p)&3 THIS iteration.
                // So stage only pair p+2's tiles AFTER compute is done with pair p,
                // i.e. next iteration. Stage pair p+2 here is unsafe; stage pair
                // p+1 was done last iteration. Instead stage pair p+2 next iter:
                // we stage tiles (2p+4,2p+5) at iteration p+1. Here stage nothing
                // extra; A slots hold pairs p (being read) and p+1 (ready).
            }
            CP_WAIT1();              // B pair p+1 complete
        } else {
            const uint32_t a0 = bAbf + (uint32_t)((2 * p) & 3) * ABF_ST;
            const uint32_t a1 = bAbf + (uint32_t)((2 * p + 1) & 3) * ABF_ST;
            const uint32_t b0 = bB + (uint32_t)sB * B_ST;
            const uint32_t b1 = b0 + B_ST;
            COMPUTE_TILE(a0, b0);
            COMPUTE_TILE(a1, b1);
        }
        __syncthreads();             // pair p consumed; pair p+1 published
        if (!isCompute && p + 2 < NP) {
            // now slots (2p)&3, (2p+1)&3 are free -> stage pair p+2 there
            STAGE_A_TILE(2 * p + 4);
            STAGE_A_TILE(2 * p + 5);
        }
        sB    = (sB    == 4) ? 0 : sB + 2;
        sBiss = (sBiss == 4) ? 0 : sBiss + 2;
    }
    // NOTE: A staging for pair p+2 happens right after the barrier of iter p,
    // i.e. during compute of pair p+1 -> ready well before its barrier. The
    // joint barrier at end of iter p+1 publishes it for iter p+2. Correct:
    // STS (iter-p tail) -> __syncthreads (iter p+1 tail) -> ldmatrix (iter p+2).

    // ---------- merge partner accumulators via smem (reuse B ring) ----------
    __syncthreads();   // everyone done with B ring
    const uint32_t xb = bB + (uint32_t)wt * 4096 + (uint32_t)lane * 4;
    if (isCompute && kh == 0) {
#pragma unroll
        for (int mi = 0; mi < 2; mi++)
#pragma unroll
            for (int nt = 0; nt < 4; nt++)
#pragma unroll
                for (int k = 0; k < 4; k++) {
                    const int e = mi * 16 + nt * 4 + k;
                    asm volatile("st.shared.f32 [%0], %1;"
                                 :: "r"(xb + (uint32_t)e * 128), "f"(acc[mi][nt][k])
                                 : "memory");
                }
    }
    __syncthreads();

    if (isCompute && kh == 1) {
        const float C = -0.75257498915995302f;   // -2.5 / log2(10)
#pragma unroll
        for (int mi = 0; mi < 2; mi++) {
            const size_t row0 = bm0 + wmBase + mi * 16 + (lane >> 2);
#pragma unroll
            for (int nt = 0; nt < 4; nt++) {
                float part[4];
#pragma unroll
                for (int k = 0; k < 4; k++) {
                    const int e = mi * 16 + nt * 4 + k;
                    asm volatile("ld.shared.f32 %0, [%1];"
                                 : "=f"(part[k]) : "r"(xb + (uint32_t)e * 128));
                }
                const int col = wnBase + nt * 8 + (lane & 3) * 2;
                float2 v0, v1;
                v0.x = C * __log2f(acc[mi][nt][0] + part[0]);
                v0.y = C * __log2f(acc[mi][nt][1] + part[1]);
                v1.x = C * __log2f(acc[mi][nt][2] + part[2]);
                v1.y = C * __log2f(acc[mi][nt][3] + part[3]);
                *reinterpret_cast<float2*>(out + row0 * BN + col)       = v0;
                *reinterpret_cast<float2*>(out + (row0 + 8) * BN + col) = v1;
            }
        }
    }
}

extern "C" void kernel_launch(void* const* d_in, const int* in_sizes, int n_in,
                              void* d_out, int out_size) {
    const float* l_target = (const float*)d_in[0];   // [B, L] fp32
    const float* trans    = (const float*)d_in[1];   // [F, L] fp32
    const float* lam      = (const float*)d_in[2];   // [L]    fp32

    const int L = in_sizes[2];
    const int F = in_sizes[1] / L;   // 128
    const int B = in_sizes[0] / L;   // 8192
    float* out = (float*)d_out;

    cudaFuncSetAttribute(gemm_log_kernel,
                         cudaFuncAttributeMaxDynamicSharedMemorySize, DYN_SMEM);

    int total4 = (F * L) >> 2;
    wt_kernel<<<(total4 + 255) / 256, 256>>>(trans, lam, F, L);
    gemm_log_kernel<<<B / BM, THREADS, DYN_SMEM>>>(l_target, out, L);
}

// round 13
// speedup vs baseline: 3.3606x; 1.3006x over previous
#include <cuda_runtime.h>
#include <cuda_bf16.h>
#include <cstdint>

// out[b,f] = -2.5*log10( sum_l A[b,l] * (trans[f,l]*w[l]) )
// wt_kernel -> g_wt bf16 [F,L] (2MB, L2-resident)
// gemm_log_kernel: BM=64 BN=128 BK=64, 512 thr, grid 128.
//   16 warps = 4 warp-tiles (32x64: 2M x 2N) x 4-way K16 split (kh=warp&3).
//   Per warp per K16: 6 ldmatrix -> 16 mma (0.375 ldm/mma; R10 was 0.5).
//   A: LDG->pack bf16 at load->STS (conflict-free 128B rows); B: 6-slot
//   cp.async ring; one barrier per PAIR of k-tiles (R10 pipeline).
//   Final 4-way k-merge via 128KB smem exchange + log10 epilogue.
// Ruled out: gmem split-K (2x), 16-row tiles (frag x1.5), BK=128/256B rows
//   (bank conflicts), 64x64 tiles @256thr (regs 255 spill), producer/consumer
//   warp split under joint barrier (R12). tcgen05 rejected (compute_103).

#define BM 64
#define BN 128
#define BK 64
#define THREADS 512
#define B_ST   16384                  // BN*BK*2
#define ABF_ST 8192                   // BM*BK*2
#define NB_ST  6
#define OFF_ABF (NB_ST * B_ST)                     // 96KB
#define DYN_SMEM (OFF_ABF + 4 * ABF_ST + 1024)     // 129KB (>=128KB merge area)

__device__ __align__(16) __nv_bfloat16 g_wt[128 * 8192];

__global__ void wt_kernel(const float* __restrict__ trans,
                          const float* __restrict__ lam, int F, int L) {
    int i4 = blockIdx.x * blockDim.x + threadIdx.x;
    int total = (F * L) >> 2;
    if (i4 >= total) return;
    int l0 = (i4 % (L >> 2)) << 2;
    float4 t = reinterpret_cast<const float4*>(trans)[i4];
    float w[4];
#pragma unroll
    for (int j = 0; j < 4; j++) {
        int l = l0 + j;
        int hi = l + 1 < L ? l + 1 : L - 1;
        int lo = l > 0 ? l - 1 : 0;
        w[j] = 0.5f * (__ldg(lam + hi) - __ldg(lam + lo));
    }
    __nv_bfloat162 p0 = __floats2bfloat162_rn(t.x * w[0], t.y * w[1]);
    __nv_bfloat162 p1 = __floats2bfloat162_rn(t.z * w[2], t.w * w[3]);
    uint2 v = { reinterpret_cast<uint32_t&>(p0), reinterpret_cast<uint32_t&>(p1) };
    reinterpret_cast<uint2*>(g_wt)[i4] = v;
}

__device__ __forceinline__ uint32_t smem_u32(const void* p) {
    uint32_t a;
    asm("{ .reg .u64 t; cvta.to.shared.u64 t, %1; cvt.u32.u64 %0, t; }"
        : "=r"(a) : "l"(p));
    return a;
}
__device__ __forceinline__ void ldmx4(uint32_t* r, uint32_t addr) {
    asm volatile("ldmatrix.sync.aligned.m8n8.x4.shared.b16 {%0,%1,%2,%3}, [%4];\n"
                 : "=r"(r[0]), "=r"(r[1]), "=r"(r[2]), "=r"(r[3]) : "r"(addr));
}
__device__ __forceinline__ void mma16816(float* c, const uint32_t* a, const uint32_t* b) {
    asm volatile("mma.sync.aligned.m16n8k16.row.col.f32.bf16.bf16.f32 "
                 "{%0,%1,%2,%3}, {%4,%5,%6,%7}, {%8,%9}, {%0,%1,%2,%3};\n"
                 : "+f"(c[0]), "+f"(c[1]), "+f"(c[2]), "+f"(c[3])
                 : "r"(a[0]), "r"(a[1]), "r"(a[2]), "r"(a[3]), "r"(b[0]), "r"(b[1]));
}
__device__ __forceinline__ uint32_t packbf2(float x, float y) {
    __nv_bfloat162 h = __floats2bfloat162_rn(x, y);
    return reinterpret_cast<uint32_t&>(h);
}
__device__ __forceinline__ void cp16(uint32_t dst, const void* src) {
    asm volatile("cp.async.cg.shared.global [%0], [%1], 16;"
                 :: "r"(dst), "l"(src) : "memory");
}
#define CP_COMMIT() asm volatile("cp.async.commit_group;" ::: "memory")
#define CP_WAIT1()  asm volatile("cp.async.wait_group 1;" ::: "memory")

__global__ void __launch_bounds__(THREADS, 1)
gemm_log_kernel(const float* __restrict__ A, float* __restrict__ out, int K) {
    extern __shared__ char dynsmem[];
    const uint32_t base = (smem_u32(dynsmem) + 1023) & ~1023u;
    const uint32_t bB   = base;
    const uint32_t bAbf = base + OFF_ABF;

    const int tid  = threadIdx.x;
    const int lane = tid & 31;
    const int warp = tid >> 5;        // 0..15
    const int wt   = warp >> 2;       // warp-tile 0..3
    const int kh   = warp & 3;        // K16 step owned
    const int tm   = wt & 1;          // M half
    const int tn   = wt >> 1;         // N half
    const size_t bm0 = (size_t)blockIdx.x * BM;
    const int NKT = K / BK;           // 128
    const int NP  = NKT >> 1;         // 64 pairs

    // ---- A staging (R10): row ar=tid>>3 (0..63), 8 fp32 at cols 8*(tid&7)
    const int ar = tid >> 3, acg = tid & 7;
    const float4* aSrc4 = reinterpret_cast<const float4*>(A + (bm0 + ar) * (size_t)K)
                        + 2 * acg;
    const uint32_t abfrel = (uint32_t)ar * 128 + (uint32_t)((acg ^ (ar & 7)) * 16);

    // ---- B staging (R10): 2 chunks/thread/tile, conflict-free 128B rows
    uint32_t brel[2];
    const __nv_bfloat16* bsrc[2];
#pragma unroll
    for (int j = 0; j < 2; j++) {
        int id = tid + 512 * j;
        int n = id >> 3, cc = id & 7;
        brel[j] = (uint32_t)(n * 128 + ((cc ^ (n & 7)) * 16));
        bsrc[j] = g_wt + (size_t)n * K + cc * 8;
    }

    // ---- fragment rows: warp-tile rows [tm*32,+32), cols [tn*64,+64)
    int arow[2], brow[4];
#pragma unroll
    for (int mi = 0; mi < 2; mi++) arow[mi] = tm * 32 + mi * 16 + (lane & 15);
#pragma unroll
    for (int f = 0; f < 4; f++)
        brow[f] = tn * 64 + f * 16 + ((lane >> 4) << 3) + (lane & 7);
    const int ca = kh * 2 + (lane >> 4);        // A smem chunk col
    const int cb = kh * 2 + ((lane >> 3) & 1);  // B smem chunk col

    float acc[2][8][4];               // 32x64 partial (one K16 lane)
#pragma unroll
    for (int i = 0; i < 2; i++)
#pragma unroll
        for (int j = 0; j < 8; j++)
#pragma unroll
            for (int k = 0; k < 4; k++) acc[i][j][k] = 0.f;

    uint32_t fa[2][4];   // PAIR of A tiles, PRE-PACKED bf16 (4 regs/tile)

#define LOAD_PAIR(P) do {                                                     \
        const float4* _p0 = aSrc4 + (size_t)(2 * (P)) * (BK >> 2);            \
        const float4* _p1 = _p0 + (BK >> 2);                                  \
        float4 _x, _y;                                                        \
        _x = __ldg(_p0); _y = __ldg(_p0 + 1);                                 \
        fa[0][0] = packbf2(_x.x, _x.y); fa[0][1] = packbf2(_x.z, _x.w);       \
        fa[0][2] = packbf2(_y.x, _y.y); fa[0][3] = packbf2(_y.z, _y.w);       \
        _x = __ldg(_p1); _y = __ldg(_p1 + 1);                                 \
        fa[1][0] = packbf2(_x.x, _x.y); fa[1][1] = packbf2(_x.z, _x.w);       \
        fa[1][2] = packbf2(_y.x, _y.y); fa[1][3] = packbf2(_y.z, _y.w);       \
    } while (0)

#define CONVERT_PAIR(P) do {                                                  \
        _Pragma("unroll")                                                     \
        for (int _t = 0; _t < 2; _t++) {                                      \
            const uint32_t _da = bAbf + (uint32_t)(((2 * (P) + _t) & 3)) * ABF_ST; \
            asm volatile("st.shared.v4.b32 [%0], {%1,%2,%3,%4};" ::           \
                "r"(_da + abfrel), "r"(fa[_t][0]), "r"(fa[_t][1]),            \
                "r"(fa[_t][2]), "r"(fa[_t][3]) : "memory");                   \
        }                                                                     \
    } while (0)

#define ISSUE_B_PAIR(P, S0) do {                                              \
        const uint32_t _b0 = bB + (uint32_t)(S0) * B_ST;                      \
        const uint32_t _b1 = _b0 + B_ST;                                      \
        const size_t _o0 = (size_t)(2 * (P)) * BK;                            \
        _Pragma("unroll")                                                     \
        for (int _j = 0; _j < 2; _j++) {                                      \
            cp16(_b0 + brel[_j], bsrc[_j] + _o0);                             \
            cp16(_b1 + brel[_j], bsrc[_j] + _o0 + BK);                        \
        }                                                                     \
    } while (0)

    // this warp's single K16 step of one k-tile: 6 ldmatrix -> 16 mma
#define COMPUTE_TILE(AOFF, BOFF) do {                                         \
        uint32_t a[2][4], b[4][4];                                            \
        _Pragma("unroll")                                                     \
        for (int _mi = 0; _mi < 2; _mi++)                                     \
            ldmx4(a[_mi], (AOFF) + (uint32_t)(arow[_mi] * 8 + (ca ^ (arow[_mi] & 7))) * 16); \
        _Pragma("unroll")                                                     \
        for (int _f = 0; _f < 4; _f++)                                        \
            ldmx4(b[_f], (BOFF) + (uint32_t)(brow[_f] * 8 + (cb ^ (brow[_f] & 7))) * 16); \
        _Pragma("unroll")                                                     \
        for (int _mi = 0; _mi < 2; _mi++)                                     \
            _Pragma("unroll")                                                 \
            for (int _nt = 0; _nt < 8; _nt++)                                 \
                mma16816(acc[_mi][_nt], a[_mi], &b[_nt >> 1][(_nt & 1) * 2]); \
    } while (0)

    // ---------- prologue ----------
    LOAD_PAIR(0);
    ISSUE_B_PAIR(0, 0); CP_COMMIT();
    ISSUE_B_PAIR(1, 2); CP_COMMIT();
    CONVERT_PAIR(0);
    CP_WAIT1();
    __syncthreads();

    int sB = 0, sBiss = 4;

    // ---------- main loop: one barrier per PAIR of k-tiles ----------
    for (int p = 0; p < NP; p++) {
        if (p + 1 < NP) LOAD_PAIR(p + 1);
        if (p + 2 < NP) ISSUE_B_PAIR(p + 2, sBiss);
        CP_COMMIT();

        const uint32_t a0 = bAbf + (uint32_t)((2 * p) & 3) * ABF_ST;
        const uint32_t a1 = bAbf + (uint32_t)((2 * p + 1) & 3) * ABF_ST;
        const uint32_t b0 = bB + (uint32_t)sB * B_ST;
        const uint32_t b1 = b0 + B_ST;

        COMPUTE_TILE(a0, b0);
        if (p + 1 < NP) CONVERT_PAIR(p + 1);
        COMPUTE_TILE(a1, b1);

        CP_WAIT1();
        __syncthreads();

        sB    = (sB    == 4) ? 0 : sB + 2;
        sBiss = (sBiss == 4) ? 0 : sBiss + 2;
    }

    // ---------- 4-way k-merge via smem (reuses ALL rings; 16 x 8KB) ----------
    __syncthreads();   // all cp.async retired (<=1 empty group), rings free
    const uint32_t region = base + (uint32_t)(wt * 4 + kh) * 8192;
#pragma unroll
    for (int mi = 0; mi < 2; mi++)
#pragma unroll
        for (int nt = 0; nt < 8; nt++)
            asm volatile("st.shared.v4.b32 [%0], {%1,%2,%3,%4};" ::
                "r"(region + (uint32_t)((mi * 8 + nt) * 512) + (uint32_t)lane * 16),
                "r"(__float_as_uint(acc[mi][nt][0])), "r"(__float_as_uint(acc[mi][nt][1])),
                "r"(__float_as_uint(acc[mi][nt][2])), "r"(__float_as_uint(acc[mi][nt][3]))
                : "memory");
    __syncthreads();

    // warp (wt, kh) finalizes blocks j in [kh*4, kh*4+4) of its tile
    const float C = -0.75257498915995302f;   // -2.5 / log2(10)
#pragma unroll
    for (int jj = 0; jj < 4; jj++) {
        const int j  = kh * 4 + jj;          // 0..15
        const int mi = j >> 3, nt = j & 7;
        float s0 = 0.f, s1 = 0.f, s2 = 0.f, s3 = 0.f;
#pragma unroll
        for (int r = 0; r < 4; r++) {
            float p0, p1, p2, p3;
            asm volatile("ld.shared.v4.f32 {%0,%1,%2,%3}, [%4];"
                : "=f"(p0), "=f"(p1), "=f"(p2), "=f"(p3)
                : "r"(base + (uint32_t)(wt * 4 + r) * 8192 +
                      (uint32_t)(j * 512) + (uint32_t)lane * 16));
            s0 += p0; s1 += p1; s2 += p2; s3 += p3;
        }
        const size_t row0 = bm0 + tm * 32 + mi * 16 + (lane >> 2);
        const int col = tn * 64 + nt * 8 + (lane & 3) * 2;
        float2 v0, v1;
        v0.x = C * __log2f(s0);
        v0.y = C * __log2f(s1);
        v1.x = C * __log2f(s2);
        v1.y = C * __log2f(s3);
        *reinterpret_cast<float2*>(out + row0 * BN + col)       = v0;
        *reinterpret_cast<float2*>(out + (row0 + 8) * BN + col) = v1;
    }
}

extern "C" void kernel_launch(void* const* d_in, const int* in_sizes, int n_in,
                              void* d_out, int out_size) {
    const float* l_target = (const float*)d_in[0];   // [B, L] fp32
    const float* trans    = (const float*)d_in[1];   // [F, L] fp32
    const float* lam      = (const float*)d_in[2];   // [L]    fp32

    const int L = in_sizes[2];
    const int F = in_sizes[1] / L;   // 128
    const int B = in_sizes[0] / L;   // 8192
    float* out = (float*)d_out;

    cudaFuncSetAttribute(gemm_log_kernel,
                         cudaFuncAttributeMaxDynamicSharedMemorySize, DYN_SMEM);

    int total4 = (F * L) >> 2;
    wt_kernel<<<(total4 + 255) / 256, 256>>>(trans, lam, F, L);
    gemm_log_kernel<<<B / BM, THREADS, DYN_SMEM>>>(l_target, out, L);
}

// round 14
// speedup vs baseline: 3.9770x; 1.1834x over previous
#include <cuda_runtime.h>
#include <cuda_bf16.h>
#include <cstdint>

// out[b,f] = -2.5*log10( sum_l A[b,l] * (trans[f,l]*w[l]) )
// wt_kernel -> g_wt bf16 [F,L] (2MB, L2-resident)
// gemm_log_kernel: BM=32 BN=128 BK=64, 256 thr, grid 256 -> 2 CTAs/SM.
//   8 warps = 4 N-tiles (32x32) x warp-pair K16 split (R10 compute scheme).
//   A: LDG->pack bf16->STS (conflict-free 128B rows); B: 4-slot cp.async ring
//   (issue depth 1, window >= one pair-compute); one barrier per k-tile PAIR.
//   Partner-merge epilogue via smem + -2.5*log10.
// Ruled out: gmem split-K (2x), 16-row tiles, BK=128/256B rows (conflicts),
//   64x64 tiles @256thr (spill), producer/consumer warps under joint barrier,
//   32x64 tiles (R13: L1 not binding). tcgen05 rejected (compute_103 target).

#define BM 32
#define BN 128
#define BK 64
#define THREADS 256
#define B_ST   16384                  // BN*BK*2
#define ABF_ST 4096                   // BM*BK*2
#define OFF_ABF (4 * B_ST)            // B: 4 slots (64KB), A: 4 slots (16KB)
#define DYN_SMEM (OFF_ABF + 4 * ABF_ST + 1024)   // ~81KB -> 2 CTAs/SM

__device__ __align__(16) __nv_bfloat16 g_wt[128 * 8192];

__global__ void wt_kernel(const float* __restrict__ trans,
                          const float* __restrict__ lam, int F, int L) {
    int i4 = blockIdx.x * blockDim.x + threadIdx.x;
    int total = (F * L) >> 2;
    if (i4 >= total) return;
    int l0 = (i4 % (L >> 2)) << 2;
    float4 t = reinterpret_cast<const float4*>(trans)[i4];
    float w[4];
#pragma unroll
    for (int j = 0; j < 4; j++) {
        int l = l0 + j;
        int hi = l + 1 < L ? l + 1 : L - 1;
        int lo = l > 0 ? l - 1 : 0;
        w[j] = 0.5f * (__ldg(lam + hi) - __ldg(lam + lo));
    }
    __nv_bfloat162 p0 = __floats2bfloat162_rn(t.x * w[0], t.y * w[1]);
    __nv_bfloat162 p1 = __floats2bfloat162_rn(t.z * w[2], t.w * w[3]);
    uint2 v = { reinterpret_cast<uint32_t&>(p0), reinterpret_cast<uint32_t&>(p1) };
    reinterpret_cast<uint2*>(g_wt)[i4] = v;
}

__device__ __forceinline__ uint32_t smem_u32(const void* p) {
    uint32_t a;
    asm("{ .reg .u64 t; cvta.to.shared.u64 t, %1; cvt.u32.u64 %0, t; }"
        : "=r"(a) : "l"(p));
    return a;
}
__device__ __forceinline__ void ldmx4(uint32_t* r, uint32_t addr) {
    asm volatile("ldmatrix.sync.aligned.m8n8.x4.shared.b16 {%0,%1,%2,%3}, [%4];\n"
                 : "=r"(r[0]), "=r"(r[1]), "=r"(r[2]), "=r"(r[3]) : "r"(addr));
}
__device__ __forceinline__ void mma16816(float* c, const uint32_t* a, const uint32_t* b) {
    asm volatile("mma.sync.aligned.m16n8k16.row.col.f32.bf16.bf16.f32 "
                 "{%0,%1,%2,%3}, {%4,%5,%6,%7}, {%8,%9}, {%0,%1,%2,%3};\n"
                 : "+f"(c[0]), "+f"(c[1]), "+f"(c[2]), "+f"(c[3])
                 : "r"(a[0]), "r"(a[1]), "r"(a[2]), "r"(a[3]), "r"(b[0]), "r"(b[1]));
}
__device__ __forceinline__ uint32_t packbf2(float x, float y) {
    __nv_bfloat162 h = __floats2bfloat162_rn(x, y);
    return reinterpret_cast<uint32_t&>(h);
}
__device__ __forceinline__ void cp16(uint32_t dst, const void* src) {
    asm volatile("cp.async.cg.shared.global [%0], [%1], 16;"
                 :: "r"(dst), "l"(src) : "memory");
}
#define CP_COMMIT() asm volatile("cp.async.commit_group;" ::: "memory")
#define CP_WAIT0()  asm volatile("cp.async.wait_group 0;" ::: "memory")

__global__ void __launch_bounds__(THREADS, 2)
gemm_log_kernel(const float* __restrict__ A, float* __restrict__ out, int K) {
    extern __shared__ char dynsmem[];
    const uint32_t base = (smem_u32(dynsmem) + 1023) & ~1023u;
    const uint32_t bB   = base;
    const uint32_t bAbf = base + OFF_ABF;

    const int tid  = threadIdx.x;
    const int lane = tid & 31;
    const int warp = tid >> 5;        // 0..7
    const int wt   = warp >> 1;       // N quarter 0..3
    const int kh   = warp & 1;        // k-half
    const size_t bm0 = (size_t)blockIdx.x * BM;
    const int NKT = K / BK;           // 128
    const int NP  = NKT >> 1;         // 64 pairs

    // ---- A staging: row ar = tid>>3 (0..31), 8 fp32 at cols 8*(tid&7)
    const int ar = tid >> 3, acg = tid & 7;
    const float4* aSrc4 = reinterpret_cast<const float4*>(A + (bm0 + ar) * (size_t)K)
                        + 2 * acg;
    const uint32_t abfrel = (uint32_t)ar * 128 + (uint32_t)((acg ^ (ar & 7)) * 16);

    // ---- B staging: 4 chunks/thread/tile, conflict-free 128B rows
    uint32_t brel[4];
    const __nv_bfloat16* bsrc[4];
#pragma unroll
    for (int j = 0; j < 4; j++) {
        int id = tid + 256 * j;
        int n = id >> 3, cc = id & 7;
        brel[j] = (uint32_t)(n * 128 + ((cc ^ (n & 7)) * 16));
        bsrc[j] = g_wt + (size_t)n * K + cc * 8;
    }

    // ---- warp tile: rows 0..31, cols [wt*32, wt*32+32); pair splits K16
    int arow[2], brow[2];
#pragma unroll
    for (int mi = 0; mi < 2; mi++) arow[mi] = mi * 16 + (lane & 15);
#pragma unroll
    for (int nj = 0; nj < 2; nj++) brow[nj] = wt * 32 + nj * 16 + ((lane >> 4) << 3) + (lane & 7);
    const int achalf = lane >> 4;
    const int bchalf = (lane >> 3) & 1;
    const int ks0 = kh * 2;

    float acc[2][4][4];
#pragma unroll
    for (int i = 0; i < 2; i++)
#pragma unroll
        for (int j = 0; j < 4; j++)
#pragma unroll
            for (int k = 0; k < 4; k++) acc[i][j][k] = 0.f;

    uint32_t fa[2][4];   // PAIR of A tiles, pre-packed bf16

#define LOAD_PAIR(P) do {                                                     \
        const float4* _p0 = aSrc4 + (size_t)(2 * (P)) * (BK >> 2);            \
        const float4* _p1 = _p0 + (BK >> 2);                                  \
        float4 _x, _y;                                                        \
        _x = __ldg(_p0); _y = __ldg(_p0 + 1);                                 \
        fa[0][0] = packbf2(_x.x, _x.y); fa[0][1] = packbf2(_x.z, _x.w);       \
        fa[0][2] = packbf2(_y.x, _y.y); fa[0][3] = packbf2(_y.z, _y.w);       \
        _x = __ldg(_p1); _y = __ldg(_p1 + 1);                                 \
        fa[1][0] = packbf2(_x.x, _x.y); fa[1][1] = packbf2(_x.z, _x.w);       \
        fa[1][2] = packbf2(_y.x, _y.y); fa[1][3] = packbf2(_y.z, _y.w);       \
    } while (0)

#define CONVERT_PAIR(P) do {                                                  \
        _Pragma("unroll")                                                     \
        for (int _t = 0; _t < 2; _t++) {                                      \
            const uint32_t _da = bAbf + (uint32_t)(((2 * (P) + _t) & 3)) * ABF_ST; \
            asm volatile("st.shared.v4.b32 [%0], {%1,%2,%3,%4};" ::           \
                "r"(_da + abfrel), "r"(fa[_t][0]), "r"(fa[_t][1]),            \
                "r"(fa[_t][2]), "r"(fa[_t][3]) : "memory");                   \
        }                                                                     \
    } while (0)

#define ISSUE_B_PAIR(P, S0) do {                                              \
        const uint32_t _b0 = bB + (uint32_t)(S0) * B_ST;                      \
        const uint32_t _b1 = _b0 + B_ST;                                      \
        const size_t _o0 = (size_t)(2 * (P)) * BK;                            \
        _Pragma("unroll")                                                     \
        for (int _j = 0; _j < 4; _j++) {                                      \
            cp16(_b0 + brel[_j], bsrc[_j] + _o0);                             \
            cp16(_b1 + brel[_j], bsrc[_j] + _o0 + BK);                        \
        }                                                                     \
    } while (0)

    // this warp's 2 K16 steps of one k-tile (R10 scheme)
#define COMPUTE_TILE(AOFF, BOFF) do {                                         \
        _Pragma("unroll")                                                     \
        for (int _s = 0; _s < 2; _s++) {                                      \
            const int ks = ks0 + _s;                                          \
            uint32_t a[2][4], b[2][4];                                        \
            _Pragma("unroll")                                                 \
            for (int mi = 0; mi < 2; mi++) {                                  \
                int c = ks * 2 + achalf;                                      \
                ldmx4(a[mi], (AOFF) + (uint32_t)(arow[mi] * 8 + (c ^ (arow[mi] & 7))) * 16); \
            }                                                                 \
            _Pragma("unroll")                                                 \
            for (int nj = 0; nj < 2; nj++) {                                  \
                int c = ks * 2 + bchalf;                                      \
                ldmx4(b[nj], (BOFF) + (uint32_t)(brow[nj] * 8 + (c ^ (brow[nj] & 7))) * 16); \
            }                                                                 \
            _Pragma("unroll")                                                 \
            for (int mi = 0; mi < 2; mi++)                                    \
                _Pragma("unroll")                                             \
                for (int nt = 0; nt < 4; nt++)                                \
                    mma16816(acc[mi][nt], a[mi], &b[nt >> 1][(nt & 1) * 2]);  \
        }                                                                     \
    } while (0)

    // ---------- prologue ----------
    LOAD_PAIR(0);
    ISSUE_B_PAIR(0, 0); CP_COMMIT();
    CONVERT_PAIR(0);
    CP_WAIT0();
    __syncthreads();

    // ---------- main loop: one barrier per PAIR; issue depth 1 ----------
    for (int p = 0; p < NP; p++) {
        if (p + 1 < NP) {
            LOAD_PAIR(p + 1);
            ISSUE_B_PAIR(p + 1, ((p + 1) & 1) * 2);
        }
        CP_COMMIT();

        const uint32_t a0 = bAbf + (uint32_t)((2 * p) & 3) * ABF_ST;
        const uint32_t a1 = bAbf + (uint32_t)((2 * p + 1) & 3) * ABF_ST;
        const uint32_t b0 = bB + (uint32_t)((p & 1) * 2) * B_ST;
        const uint32_t b1 = b0 + B_ST;

        COMPUTE_TILE(a0, b0);
        if (p + 1 < NP) CONVERT_PAIR(p + 1);
        COMPUTE_TILE(a1, b1);

        CP_WAIT0();                   // pair p+1's B complete
        __syncthreads();              // publish pair p+1; free pair p slots
    }

    // ---------- partner merge (kh=0 -> kh=1) via smem, then epilogue ----------
    __syncthreads();   // B ring free
    const uint32_t xb = bB + (uint32_t)wt * 4096 + (uint32_t)lane * 4;
    if (kh == 0) {
#pragma unroll
        for (int mi = 0; mi < 2; mi++)
#pragma unroll
            for (int nt = 0; nt < 4; nt++)
#pragma unroll
                for (int k = 0; k < 4; k++) {
                    const int e = mi * 16 + nt * 4 + k;
                    asm volatile("st.shared.f32 [%0], %1;"
                                 :: "r"(xb + (uint32_t)e * 128), "f"(acc[mi][nt][k])
                                 : "memory");
                }
    }
    __syncthreads();

    if (kh == 1) {
        const float C = -0.75257498915995302f;   // -2.5 / log2(10)
#pragma unroll
        for (int mi = 0; mi < 2; mi++) {
            const size_t row0 = bm0 + mi * 16 + (lane >> 2);
#pragma unroll
            for (int nt = 0; nt < 4; nt++) {
                float part[4];
#pragma unroll
                for (int k = 0; k < 4; k++) {
                    const int e = mi * 16 + nt * 4 + k;
                    asm volatile("ld.shared.f32 %0, [%1];"
                                 : "=f"(part[k]) : "r"(xb + (uint32_t)e * 128));
                }
                const int col = wt * 32 + nt * 8 + (lane & 3) * 2;
                float2 v0, v1;
                v0.x = C * __log2f(acc[mi][nt][0] + part[0]);
                v0.y = C * __log2f(acc[mi][nt][1] + part[1]);
                v1.x = C * __log2f(acc[mi][nt][2] + part[2]);
                v1.y = C * __log2f(acc[mi][nt][3] + part[3]);
                *reinterpret_cast<float2*>(out + row0 * BN + col)       = v0;
                *reinterpret_cast<float2*>(out + (row0 + 8) * BN + col) = v1;
            }
        }
    }
}

extern "C" void kernel_launch(void* const* d_in, const int* in_sizes, int n_in,
                              void* d_out, int out_size) {
    const float* l_target = (const float*)d_in[0];   // [B, L] fp32
    const float* trans    = (const float*)d_in[1];   // [F, L] fp32
    const float* lam      = (const float*)d_in[2];   // [L]    fp32

    const int L = in_sizes[2];
    const int F = in_sizes[1] / L;   // 128
    const int B = in_sizes[0] / L;   // 8192
    float* out = (float*)d_out;

    cudaFuncSetAttribute(gemm_log_kernel,
                         cudaFuncAttributeMaxDynamicSharedMemorySize, DYN_SMEM);

    int total4 = (F * L) >> 2;
    wt_kernel<<<(total4 + 255) / 256, 256>>>(trans, lam, F, L);
    gemm_log_kernel<<<B / BM, THREADS, DYN_SMEM>>>(l_target, out, L);
}

// round 15
// speedup vs baseline: 4.0033x; 1.0066x over previous
#include <cuda_runtime.h>
#include <cuda_bf16.h>
#include <cstdint>

// out[b,f] = -2.5*log10( sum_l A[b,l] * (trans[f,l]*w[l]) )
// wt_kernel -> g_wt bf16 [F,L] (2MB, L2-resident)
// gemm_log_kernel: R14 structure (BM=32 BN=128 BK=64, 256 thr, grid 256,
//   2 CTAs/SM, 4 N-tiles x warp-pair K16 split, 4-slot B ring, 1 barrier/pair)
//   + WIDER IN-WARP ILP: both K16 steps' 8 ldmatrix issued up front, then 16
//   back-to-back mma; A-convert STS slotted into the ldm shadow.
// Ruled out: gmem split-K, 16-row tiles, BK=128/256B rows (conflicts), 64x64
//   tiles (spill), producer warps under joint barrier, 32x64 tiles (L1 not
//   binding). tcgen05 rejected (compute_103 target).

#define BM 32
#define BN 128
#define BK 64
#define THREADS 256
#define B_ST   16384                  // BN*BK*2
#define ABF_ST 4096                   // BM*BK*2
#define OFF_ABF (4 * B_ST)            // B: 4 slots (64KB), A: 4 slots (16KB)
#define DYN_SMEM (OFF_ABF + 4 * ABF_ST + 1024)   // ~81KB -> 2 CTAs/SM

__device__ __align__(16) __nv_bfloat16 g_wt[128 * 8192];

__global__ void wt_kernel(const float* __restrict__ trans,
                          const float* __restrict__ lam, int F, int L) {
    int i4 = blockIdx.x * blockDim.x + threadIdx.x;
    int total = (F * L) >> 2;
    if (i4 >= total) return;
    int l0 = (i4 % (L >> 2)) << 2;
    float4 t = reinterpret_cast<const float4*>(trans)[i4];
    float w[4];
#pragma unroll
    for (int j = 0; j < 4; j++) {
        int l = l0 + j;
        int hi = l + 1 < L ? l + 1 : L - 1;
        int lo = l > 0 ? l - 1 : 0;
        w[j] = 0.5f * (__ldg(lam + hi) - __ldg(lam + lo));
    }
    __nv_bfloat162 p0 = __floats2bfloat162_rn(t.x * w[0], t.y * w[1]);
    __nv_bfloat162 p1 = __floats2bfloat162_rn(t.z * w[2], t.w * w[3]);
    uint2 v = { reinterpret_cast<uint32_t&>(p0), reinterpret_cast<uint32_t&>(p1) };
    reinterpret_cast<uint2*>(g_wt)[i4] = v;
}

__device__ __forceinline__ uint32_t smem_u32(const void* p) {
    uint32_t a;
    asm("{ .reg .u64 t; cvta.to.shared.u64 t, %1; cvt.u32.u64 %0, t; }"
        : "=r"(a) : "l"(p));
    return a;
}
__device__ __forceinline__ void ldmx4(uint32_t* r, uint32_t addr) {
    asm volatile("ldmatrix.sync.aligned.m8n8.x4.shared.b16 {%0,%1,%2,%3}, [%4];\n"
                 : "=r"(r[0]), "=r"(r[1]), "=r"(r[2]), "=r"(r[3]) : "r"(addr));
}
__device__ __forceinline__ void mma16816(float* c, const uint32_t* a, const uint32_t* b) {
    asm volatile("mma.sync.aligned.m16n8k16.row.col.f32.bf16.bf16.f32 "
                 "{%0,%1,%2,%3}, {%4,%5,%6,%7}, {%8,%9}, {%0,%1,%2,%3};\n"
                 : "+f"(c[0]), "+f"(c[1]), "+f"(c[2]), "+f"(c[3])
                 : "r"(a[0]), "r"(a[1]), "r"(a[2]), "r"(a[3]), "r"(b[0]), "r"(b[1]));
}
__device__ __forceinline__ uint32_t packbf2(float x, float y) {
    __nv_bfloat162 h = __floats2bfloat162_rn(x, y);
    return reinterpret_cast<uint32_t&>(h);
}
__device__ __forceinline__ void cp16(uint32_t dst, const void* src) {
    asm volatile("cp.async.cg.shared.global [%0], [%1], 16;"
                 :: "r"(dst), "l"(src) : "memory");
}
#define CP_COMMIT() asm volatile("cp.async.commit_group;" ::: "memory")
#define CP_WAIT0()  asm volatile("cp.async.wait_group 0;" ::: "memory")

__global__ void __launch_bounds__(THREADS, 2)
gemm_log_kernel(const float* __restrict__ A, float* __restrict__ out, int K) {
    extern __shared__ char dynsmem[];
    const uint32_t base = (smem_u32(dynsmem) + 1023) & ~1023u;
    const uint32_t bB   = base;
    const uint32_t bAbf = base + OFF_ABF;

    const int tid  = threadIdx.x;
    const int lane = tid & 31;
    const int warp = tid >> 5;        // 0..7
    const int wt   = warp >> 1;       // N quarter 0..3
    const int kh   = warp & 1;        // k-half
    const size_t bm0 = (size_t)blockIdx.x * BM;
    const int NKT = K / BK;           // 128
    const int NP  = NKT >> 1;         // 64 pairs

    // ---- A staging: row ar = tid>>3 (0..31), 8 fp32 at cols 8*(tid&7)
    const int ar = tid >> 3, acg = tid & 7;
    const float4* aSrc4 = reinterpret_cast<const float4*>(A + (bm0 + ar) * (size_t)K)
                        + 2 * acg;
    const uint32_t abfrel = (uint32_t)ar * 128 + (uint32_t)((acg ^ (ar & 7)) * 16);

    // ---- B staging: 4 chunks/thread/tile, conflict-free 128B rows
    uint32_t brel[4];
    const __nv_bfloat16* bsrc[4];
#pragma unroll
    for (int j = 0; j < 4; j++) {
        int id = tid + 256 * j;
        int n = id >> 3, cc = id & 7;
        brel[j] = (uint32_t)(n * 128 + ((cc ^ (n & 7)) * 16));
        bsrc[j] = g_wt + (size_t)n * K + cc * 8;
    }

    // ---- warp tile: rows 0..31, cols [wt*32, wt*32+32); pair splits K16
    int arow[2], brow[2];
#pragma unroll
    for (int mi = 0; mi < 2; mi++) arow[mi] = mi * 16 + (lane & 15);
#pragma unroll
    for (int nj = 0; nj < 2; nj++) brow[nj] = wt * 32 + nj * 16 + ((lane >> 4) << 3) + (lane & 7);
    const int achalf = lane >> 4;
    const int bchalf = (lane >> 3) & 1;
    const int ks0 = kh * 2;

    float acc[2][4][4];
#pragma unroll
    for (int i = 0; i < 2; i++)
#pragma unroll
        for (int j = 0; j < 4; j++)
#pragma unroll
            for (int k = 0; k < 4; k++) acc[i][j][k] = 0.f;

    uint32_t fa[2][4];   // PAIR of A tiles, pre-packed bf16

#define LOAD_PAIR(P) do {                                                     \
        const float4* _p0 = aSrc4 + (size_t)(2 * (P)) * (BK >> 2);            \
        const float4* _p1 = _p0 + (BK >> 2);                                  \
        float4 _x, _y;                                                        \
        _x = __ldg(_p0); _y = __ldg(_p0 + 1);                                 \
        fa[0][0] = packbf2(_x.x, _x.y); fa[0][1] = packbf2(_x.z, _x.w);       \
        fa[0][2] = packbf2(_y.x, _y.y); fa[0][3] = packbf2(_y.z, _y.w);       \
        _x = __ldg(_p1); _y = __ldg(_p1 + 1);                                 \
        fa[1][0] = packbf2(_x.x, _x.y); fa[1][1] = packbf2(_x.z, _x.w);       \
        fa[1][2] = packbf2(_y.x, _y.y); fa[1][3] = packbf2(_y.z, _y.w);       \
    } while (0)

#define CONVERT_PAIR(P) do {                                                  \
        _Pragma("unroll")                                                     \
        for (int _t = 0; _t < 2; _t++) {                                      \
            const uint32_t _da = bAbf + (uint32_t)(((2 * (P) + _t) & 3)) * ABF_ST; \
            asm volatile("st.shared.v4.b32 [%0], {%1,%2,%3,%4};" ::           \
                "r"(_da + abfrel), "r"(fa[_t][0]), "r"(fa[_t][1]),            \
                "r"(fa[_t][2]), "r"(fa[_t][3]) : "memory");                   \
        }                                                                     \
    } while (0)

#define ISSUE_B_PAIR(P, S0) do {                                              \
        const uint32_t _b0 = bB + (uint32_t)(S0) * B_ST;                      \
        const uint32_t _b1 = _b0 + B_ST;                                      \
        const size_t _o0 = (size_t)(2 * (P)) * BK;                            \
        _Pragma("unroll")                                                     \
        for (int _j = 0; _j < 4; _j++) {                                      \
            cp16(_b0 + brel[_j], bsrc[_j] + _o0);                             \
            cp16(_b1 + brel[_j], bsrc[_j] + _o0 + BK);                        \
        }                                                                     \
    } while (0)

    // ldm for BOTH K16 steps of one tile up front (8 ldm), into a/b[2][..]
#define LDFRAG_TILE(AOFF, BOFF, a, b) do {                                    \
        _Pragma("unroll")                                                     \
        for (int _s = 0; _s < 2; _s++) {                                      \
            const int ks = ks0 + _s;                                          \
            const int _ca = ks * 2 + achalf;                                  \
            const int _cb = ks * 2 + bchalf;                                  \
            _Pragma("unroll")                                                 \
            for (int mi = 0; mi < 2; mi++)                                    \
                ldmx4((a)[_s][mi], (AOFF) + (uint32_t)(arow[mi] * 8 + (_ca ^ (arow[mi] & 7))) * 16); \
            _Pragma("unroll")                                                 \
            for (int nj = 0; nj < 2; nj++)                                    \
                ldmx4((b)[_s][nj], (BOFF) + (uint32_t)(brow[nj] * 8 + (_cb ^ (brow[nj] & 7))) * 16); \
        }                                                                     \
    } while (0)

#define MMA_TILE(a, b) do {                                                   \
        _Pragma("unroll")                                                     \
        for (int _s = 0; _s < 2; _s++)                                        \
            _Pragma("unroll")                                                 \
            for (int mi = 0; mi < 2; mi++)                                    \
                _Pragma("unroll")                                             \
                for (int nt = 0; nt < 4; nt++)                                \
                    mma16816(acc[mi][nt], (a)[_s][mi], &(b)[_s][nt >> 1][(nt & 1) * 2]); \
    } while (0)

    // ---------- prologue ----------
    LOAD_PAIR(0);
    ISSUE_B_PAIR(0, 0); CP_COMMIT();
    CONVERT_PAIR(0);
    CP_WAIT0();
    __syncthreads();

    // ---------- main loop: one barrier per PAIR; issue depth 1 ----------
    for (int p = 0; p < NP; p++) {
        if (p + 1 < NP) {
            LOAD_PAIR(p + 1);
            ISSUE_B_PAIR(p + 1, ((p + 1) & 1) * 2);
        }
        CP_COMMIT();

        const uint32_t a0 = bAbf + (uint32_t)((2 * p) & 3) * ABF_ST;
        const uint32_t a1 = bAbf + (uint32_t)((2 * p + 1) & 3) * ABF_ST;
        const uint32_t b0 = bB + (uint32_t)((p & 1) * 2) * B_ST;
        const uint32_t b1 = b0 + B_ST;

        {
            uint32_t a[2][2][4], b[2][2][4];
            LDFRAG_TILE(a0, b0, a, b);          // 8 ldm in flight
            if (p + 1 < NP) CONVERT_PAIR(p + 1); // STS filler in ldm shadow
            MMA_TILE(a, b);                      // 16 back-to-back mma
        }
        {
            uint32_t a[2][2][4], b[2][2][4];
            LDFRAG_TILE(a1, b1, a, b);
            MMA_TILE(a, b);
        }

        CP_WAIT0();                   // pair p+1's B complete
        __syncthreads();              // publish pair p+1; free pair p slots
    }

    // ---------- partner merge (kh=0 -> kh=1) via smem, then epilogue ----------
    __syncthreads();   // B ring free
    const uint32_t xb = bB + (uint32_t)wt * 4096 + (uint32_t)lane * 4;
    if (kh == 0) {
#pragma unroll
        for (int mi = 0; mi < 2; mi++)
#pragma unroll
            for (int nt = 0; nt < 4; nt++)
#pragma unroll
                for (int k = 0; k < 4; k++) {
                    const int e = mi * 16 + nt * 4 + k;
                    asm volatile("st.shared.f32 [%0], %1;"
                                 :: "r"(xb + (uint32_t)e * 128), "f"(acc[mi][nt][k])
                                 : "memory");
                }
    }
    __syncthreads();

    if (kh == 1) {
        const float C = -0.75257498915995302f;   // -2.5 / log2(10)
#pragma unroll
        for (int mi = 0; mi < 2; mi++) {
            const size_t row0 = bm0 + mi * 16 + (lane >> 2);
#pragma unroll
            for (int nt = 0; nt < 4; nt++) {
                float part[4];
#pragma unroll
                for (int k = 0; k < 4; k++) {
                    const int e = mi * 16 + nt * 4 + k;
                    asm volatile("ld.shared.f32 %0, [%1];"
                                 : "=f"(part[k]) : "r"(xb + (uint32_t)e * 128));
                }
                const int col = wt * 32 + nt * 8 + (lane & 3) * 2;
                float2 v0, v1;
                v0.x = C * __log2f(acc[mi][nt][0] + part[0]);
                v0.y = C * __log2f(acc[mi][nt][1] + part[1]);
                v1.x = C * __log2f(acc[mi][nt][2] + part[2]);
                v1.y = C * __log2f(acc[mi][nt][3] + part[3]);
                *reinterpret_cast<float2*>(out + row0 * BN + col)       = v0;
                *reinterpret_cast<float2*>(out + (row0 + 8) * BN + col) = v1;
            }
        }
    }
}

extern "C" void kernel_launch(void* const* d_in, const int* in_sizes, int n_in,
                              void* d_out, int out_size) {
    const float* l_target = (const float*)d_in[0];   // [B, L] fp32
    const float* trans    = (const float*)d_in[1];   // [F, L] fp32
    const float* lam      = (const float*)d_in[2];   // [L]    fp32

    const int L = in_sizes[2];
    const int F = in_sizes[1] / L;   // 128
    const int B = in_sizes[0] / L;   // 8192
    float* out = (float*)d_out;

    cudaFuncSetAttribute(gemm_log_kernel,
                         cudaFuncAttributeMaxDynamicSharedMemorySize, DYN_SMEM);

    int total4 = (F * L) >> 2;
    wt_kernel<<<(total4 + 255) / 256, 256>>>(trans, lam, F, L);
    gemm_log_kernel<<<B / BM, THREADS, DYN_SMEM>>>(l_target, out, L);
}